// round 1
// baseline (speedup 1.0000x reference)
#include <cuda_runtime.h>
#include <cstdint>

#define NATOMS 50000
#define NEDGES 800000
#define FDIM   64

// scratch for x = MLP(q): [N, 192]
__device__ float g_x[NATOMS * 3 * FDIM];

// ---------------------------------------------------------------------------
// Kernel A: per-atom MLP  x = W2 * silu(W1*q + b1) + b2
// block = 256 threads, 64 atoms per block.
// Phase 1: 4x4 thread tile (64 atoms x 64 hidden). Phase 2: 4x12 tile (64 x 192).
// W1 + q/h in smem (~33KB static); W2 streamed via __ldg (48KB, L1-resident).
// ---------------------------------------------------------------------------
__global__ __launch_bounds__(256) void painn_mlp_kernel(
    const float* __restrict__ q,
    const float* __restrict__ W1, const float* __restrict__ b1,
    const float* __restrict__ W2, const float* __restrict__ b2,
    float* __restrict__ xout)
{
    __shared__ float sQ[64 * 65];   // q tile, then reused for h tile (padded)
    __shared__ float sW1[64 * 64];
    __shared__ float sB1[64];
    __shared__ float sB2[192];

    const int t = threadIdx.x;
    const int atom0 = blockIdx.x * 64;

    for (int k = t; k < 64 * 64; k += 256) sW1[k] = W1[k];
    if (t < 64)  sB1[t] = b1[t];
    if (t < 192) sB2[t] = b2[t];
    for (int k = t; k < 64 * 64; k += 256) {
        int a = k >> 6, f = k & 63;
        int ga = atom0 + a;
        sQ[a * 65 + f] = (ga < NATOMS) ? q[(size_t)ga * 64 + f] : 0.0f;
    }
    __syncthreads();

    const int tx = t & 15;   // 16 column groups
    const int ty = t >> 4;   // 16 row groups

    // ---- phase 1: h = silu(q*W1 + b1), thread tile 4 atoms x 4 cols ----
    float acc[4][4];
#pragma unroll
    for (int r = 0; r < 4; r++)
#pragma unroll
        for (int c = 0; c < 4; c++) acc[r][c] = 0.0f;

#pragma unroll 4
    for (int k = 0; k < 64; k++) {
        float4 w = *(const float4*)&sW1[k * 64 + tx * 4];
#pragma unroll
        for (int r = 0; r < 4; r++) {
            float qa = sQ[(ty * 4 + r) * 65 + k];
            acc[r][0] += qa * w.x;
            acc[r][1] += qa * w.y;
            acc[r][2] += qa * w.z;
            acc[r][3] += qa * w.w;
        }
    }
    __syncthreads();   // done reading q tile before overwrite with h

#pragma unroll
    for (int r = 0; r < 4; r++) {
#pragma unroll
        for (int c = 0; c < 4; c++) {
            float v = acc[r][c] + sB1[tx * 4 + c];
            v = v / (1.0f + __expf(-v));          // silu
            sQ[(ty * 4 + r) * 65 + tx * 4 + c] = v;
        }
    }
    __syncthreads();

    // ---- phase 2: x = h*W2 + b2, thread tile 4 atoms x 12 cols ----
    float a2[4][12];
#pragma unroll
    for (int r = 0; r < 4; r++)
#pragma unroll
        for (int c = 0; c < 12; c++) a2[r][c] = 0.0f;

    const int ocol = tx * 12;   // 16*12 = 192 output cols
#pragma unroll 2
    for (int k = 0; k < 64; k++) {
        const float4 w0 = __ldg((const float4*)&W2[k * 192 + ocol + 0]);
        const float4 w1 = __ldg((const float4*)&W2[k * 192 + ocol + 4]);
        const float4 w2 = __ldg((const float4*)&W2[k * 192 + ocol + 8]);
#pragma unroll
        for (int r = 0; r < 4; r++) {
            float h = sQ[(ty * 4 + r) * 65 + k];
            a2[r][0] += h * w0.x;  a2[r][1] += h * w0.y;
            a2[r][2] += h * w0.z;  a2[r][3] += h * w0.w;
            a2[r][4] += h * w1.x;  a2[r][5] += h * w1.y;
            a2[r][6] += h * w1.z;  a2[r][7] += h * w1.w;
            a2[r][8] += h * w2.x;  a2[r][9] += h * w2.y;
            a2[r][10] += h * w2.z; a2[r][11] += h * w2.w;
        }
    }

#pragma unroll
    for (int r = 0; r < 4; r++) {
        int atom = atom0 + ty * 4 + r;
        if (atom < NATOMS) {
            float* dst = &xout[(size_t)atom * 192 + ocol];
#pragma unroll
            for (int c = 0; c < 12; c += 4) {
                float4 v;
                v.x = a2[r][c + 0] + sB2[ocol + c + 0];
                v.y = a2[r][c + 1] + sB2[ocol + c + 1];
                v.z = a2[r][c + 2] + sB2[ocol + c + 2];
                v.w = a2[r][c + 3] + sB2[ocol + c + 3];
                *(float4*)(dst + c) = v;
            }
        }
    }
}

// ---------------------------------------------------------------------------
// Kernel B: out = concat(q, mu)  (float4 copy; atomics then accumulate on top)
// ---------------------------------------------------------------------------
__global__ __launch_bounds__(256) void painn_init_out_kernel(
    const float* __restrict__ q, const float* __restrict__ mu,
    float* __restrict__ out)
{
    const size_t NQ4 = (size_t)NATOMS * 64 / 4;       // 800000
    const size_t NT4 = (size_t)NATOMS * 256 / 4;      // 3200000
    size_t i = (size_t)blockIdx.x * blockDim.x + threadIdx.x;
    if (i < NQ4) {
        ((float4*)out)[i] = ((const float4*)q)[i];
    } else if (i < NT4) {
        ((float4*)out)[i] = ((const float4*)mu)[i - NQ4];
    }
}

// ---------------------------------------------------------------------------
// Kernel C: edge scatter. 16 lanes per edge, one float4 chunk per lane.
//   dq   = Wij[0:64]  * x_j[0:64]
//   dmuR = Wij[64:128]* x_j[64:128],  dmumu = Wij[128:192]* x_j[128:192]
//   dmu_d = dmuR*dir_d + dmumu*mu_j[d]
// Vector reductions (red.global.add.v4.f32) into out.
// ---------------------------------------------------------------------------
__device__ __forceinline__ void red4(float* p, float4 v) {
    asm volatile("red.global.add.v4.f32 [%0], {%1, %2, %3, %4};"
                 :: "l"(p), "f"(v.x), "f"(v.y), "f"(v.z), "f"(v.w)
                 : "memory");
}

__global__ __launch_bounds__(256) void painn_edge_kernel(
    const float* __restrict__ Wij, const float* __restrict__ dir_ij,
    const int* __restrict__ idx_i, const int* __restrict__ idx_j,
    const float* __restrict__ mu,  const float* __restrict__ x,
    float* __restrict__ out)
{
    const int gid = blockIdx.x * blockDim.x + threadIdx.x;
    const int e = gid >> 4;
    const int l = gid & 15;
    if (e >= NEDGES) return;

    const int i = __ldg(&idx_i[e]);
    const int j = __ldg(&idx_j[e]);

    const float4* W4 = (const float4*)(Wij + (size_t)e * 192);
    const float4* X4 = (const float4*)(x   + (size_t)j * 192);
    const float4* M4 = (const float4*)(mu  + (size_t)j * 192);

    const float4 w0 = __ldg(&W4[l]);
    const float4 w1 = __ldg(&W4[16 + l]);
    const float4 w2 = __ldg(&W4[32 + l]);
    const float4 x0 = __ldg(&X4[l]);
    const float4 x1 = __ldg(&X4[16 + l]);
    const float4 x2 = __ldg(&X4[32 + l]);

    const float dx = __ldg(&dir_ij[(size_t)e * 3 + 0]);
    const float dy = __ldg(&dir_ij[(size_t)e * 3 + 1]);
    const float dz = __ldg(&dir_ij[(size_t)e * 3 + 2]);

    float4 dq, mR, mM;
    dq.x = w0.x * x0.x; dq.y = w0.y * x0.y; dq.z = w0.z * x0.z; dq.w = w0.w * x0.w;
    mR.x = w1.x * x1.x; mR.y = w1.y * x1.y; mR.z = w1.z * x1.z; mR.w = w1.w * x1.w;
    mM.x = w2.x * x2.x; mM.y = w2.y * x2.y; mM.z = w2.z * x2.z; mM.w = w2.w * x2.w;

    // q part: out[i*64 + 4l]
    red4(out + (size_t)i * 64 + l * 4, dq);

    const float4 m0 = __ldg(&M4[l]);
    const float4 m1 = __ldg(&M4[16 + l]);
    const float4 m2 = __ldg(&M4[32 + l]);

    float* omu = out + (size_t)NATOMS * 64 + (size_t)i * 192 + l * 4;

    float4 d0, d1, d2;
    d0.x = fmaf(mR.x, dx, mM.x * m0.x); d0.y = fmaf(mR.y, dx, mM.y * m0.y);
    d0.z = fmaf(mR.z, dx, mM.z * m0.z); d0.w = fmaf(mR.w, dx, mM.w * m0.w);
    red4(omu, d0);

    d1.x = fmaf(mR.x, dy, mM.x * m1.x); d1.y = fmaf(mR.y, dy, mM.y * m1.y);
    d1.z = fmaf(mR.z, dy, mM.z * m1.z); d1.w = fmaf(mR.w, dy, mM.w * m1.w);
    red4(omu + 64, d1);

    d2.x = fmaf(mR.x, dz, mM.x * m2.x); d2.y = fmaf(mR.y, dz, mM.y * m2.y);
    d2.z = fmaf(mR.z, dz, mM.z * m2.z); d2.w = fmaf(mR.w, dz, mM.w * m2.w);
    red4(omu + 128, d2);
}

// ---------------------------------------------------------------------------
// launch
// ---------------------------------------------------------------------------
extern "C" void kernel_launch(void* const* d_in, const int* in_sizes, int n_in,
                              void* d_out, int out_size)
{
    int iq = -1, imu = -1, iW = -1, idir = -1, ii = -1, ij = -1;
    int iW1 = -1, ib1 = -1, iW2 = -1, ib2 = -1;
    for (int k = 0; k < n_in; k++) {
        long s = in_sizes[k];
        if      (s == (long)NATOMS * 64)   iq  = k;
        else if (s == (long)NATOMS * 192)  imu = k;
        else if (s == (long)NEDGES * 192)  iW  = k;
        else if (s == (long)NEDGES * 3)    idir = k;
        else if (s == (long)NEDGES)        { if (ii < 0) ii = k; else ij = k; }
        else if (s == 64 * 64)             iW1 = k;
        else if (s == 64)                  ib1 = k;
        else if (s == 64 * 192)            iW2 = k;
        else if (s == 192)                 ib2 = k;
        // s == 1 (n_atoms scalar) ignored
    }

    const float* q   = (const float*)d_in[iq];
    const float* mu  = (const float*)d_in[imu];
    const float* Wij = (const float*)d_in[iW];
    const float* dir = (const float*)d_in[idir];
    const int*  idxi = (const int*)d_in[ii];
    const int*  idxj = (const int*)d_in[ij];
    const float* W1  = (const float*)d_in[iW1];
    const float* b1  = (const float*)d_in[ib1];
    const float* W2  = (const float*)d_in[iW2];
    const float* b2  = (const float*)d_in[ib2];
    float* out = (float*)d_out;

    float* xbuf;
    cudaGetSymbolAddress((void**)&xbuf, g_x);

    // A: per-atom MLP -> g_x
    painn_mlp_kernel<<<(NATOMS + 63) / 64, 256>>>(q, W1, b1, W2, b2, xbuf);

    // B: out = concat(q, mu)
    {
        const int total4 = NATOMS * 256 / 4;
        painn_init_out_kernel<<<(total4 + 255) / 256, 256>>>(q, mu, out);
    }

    // C: edge scatter with vector reductions
    {
        const long threads = (long)NEDGES * 16;
        painn_edge_kernel<<<(int)((threads + 255) / 256), 256>>>(
            Wij, dir, idxi, idxj, mu, xbuf, out);
    }
}

// round 3
// speedup vs baseline: 1.0114x; 1.0114x over previous
#include <cuda_runtime.h>
#include <cstdint>

#define NATOMS 50000
#define NEDGES 800000
#define FDIM   64

// scratch
__device__ float g_x[NATOMS * 3 * FDIM];   // x = MLP(q), [N,192]
__device__ int   g_cnt[NATOMS];            // histogram of idx_j
__device__ int   g_off[NATOMS];            // exclusive offsets
__device__ int   g_cur[NATOMS];            // scatter cursors
__device__ int   g_perm[NEDGES];           // edge ids sorted by idx_j

// ---- packed f32x2 helpers -------------------------------------------------
#define PK2(d, lo, hi) \
    asm("mov.b64 %0, {%1, %2};" : "=l"(d) : "r"(__float_as_uint(lo)), "r"(__float_as_uint(hi)))
#define UPK2(lo, hi, d) do { unsigned _ulo, _uhi; \
    asm("mov.b64 {%0, %1}, %2;" : "=r"(_ulo), "=r"(_uhi) : "l"(d)); \
    lo = __uint_as_float(_ulo); hi = __uint_as_float(_uhi); } while (0)
#define FMA2(acc, a, b) \
    asm("fma.rn.f32x2 %0, %1, %2, %0;" : "+l"(acc) : "l"(a), "l"(b))

#define HSTRIDE 68   // row stride for 64-wide tiles: multiple of 4 (float4-aligned)

// ---------------------------------------------------------------------------
// Kernel A: per-atom MLP  x = W2 * silu(W1*q + b1) + b2
// 256 threads, 128 atoms/block. tx=col group (16), ty=row group (16 x 8 atoms).
// f32x2 packed FMAs; W1/W2 via __ldg (L1-resident).
// ---------------------------------------------------------------------------
__global__ __launch_bounds__(256) void painn_mlp_kernel(
    const float* __restrict__ q,
    const float* __restrict__ W1, const float* __restrict__ b1,
    const float* __restrict__ W2, const float* __restrict__ b2,
    float* __restrict__ xout)
{
    __shared__ float sH[128 * HSTRIDE];   // q tile, then h tile
    __shared__ float sB2[192];

    const int t = threadIdx.x;
    const int atom0 = blockIdx.x * 128;
    const int tx = t & 15;
    const int ty = t >> 4;

    // load q tile (128 x 64) into padded rows (float4-aligned slots)
    for (int k = t; k < 128 * 16; k += 256) {
        int a = k >> 4, c4 = k & 15;
        int ga = atom0 + a;
        float4 v = (ga < NATOMS) ? __ldg((const float4*)q + (size_t)ga * 16 + c4)
                                 : make_float4(0.f, 0.f, 0.f, 0.f);
        *(float4*)&sH[a * HSTRIDE + c4 * 4] = v;
    }
    if (t < 192) sB2[t] = b2[t];
    __syncthreads();

    // ---- phase 1: h = silu(q*W1 + b1), 8 atoms x 4 cols (2 pairs) ----
    unsigned long long acc1[8][2];
#pragma unroll
    for (int r = 0; r < 8; r++) { acc1[r][0] = 0ull; acc1[r][1] = 0ull; }

    const float4* W1v = (const float4*)W1;
#pragma unroll 4
    for (int k = 0; k < 64; k++) {
        float4 w = __ldg(&W1v[k * 16 + tx]);
        unsigned long long wp0, wp1;
        PK2(wp0, w.x, w.y);
        PK2(wp1, w.z, w.w);
#pragma unroll
        for (int r = 0; r < 8; r++) {
            float h = sH[(ty * 8 + r) * HSTRIDE + k];
            unsigned long long hp;
            PK2(hp, h, h);
            FMA2(acc1[r][0], hp, wp0);
            FMA2(acc1[r][1], hp, wp1);
        }
    }
    __syncthreads();   // everyone done reading q

    {
        float b0 = __ldg(&b1[tx * 4 + 0]);
        float bb1 = __ldg(&b1[tx * 4 + 1]);
        float b2v = __ldg(&b1[tx * 4 + 2]);
        float b3 = __ldg(&b1[tx * 4 + 3]);
#pragma unroll
        for (int r = 0; r < 8; r++) {
            float v0, v1, v2, v3;
            UPK2(v0, v1, acc1[r][0]);
            UPK2(v2, v3, acc1[r][1]);
            v0 += b0; v1 += bb1; v2 += b2v; v3 += b3;
            v0 = v0 / (1.0f + __expf(-v0));
            v1 = v1 / (1.0f + __expf(-v1));
            v2 = v2 / (1.0f + __expf(-v2));
            v3 = v3 / (1.0f + __expf(-v3));
            float* row = &sH[(ty * 8 + r) * HSTRIDE + tx * 4];
            row[0] = v0; row[1] = v1; row[2] = v2; row[3] = v3;
        }
    }
    __syncthreads();

    // ---- phase 2: x = h*W2 + b2, 8 atoms x 12 cols (6 pairs) ----
    unsigned long long a2[8][6];
#pragma unroll
    for (int r = 0; r < 8; r++)
#pragma unroll
        for (int c = 0; c < 6; c++) a2[r][c] = 0ull;

    const float4* W2v = (const float4*)W2;   // row stride 48 float4
    const int oc4 = tx * 3;
#pragma unroll 2
    for (int k = 0; k < 64; k++) {
        float4 wa = __ldg(&W2v[k * 48 + oc4 + 0]);
        float4 wb = __ldg(&W2v[k * 48 + oc4 + 1]);
        float4 wc = __ldg(&W2v[k * 48 + oc4 + 2]);
        unsigned long long w0, w1, w2, w3, w4, w5;
        PK2(w0, wa.x, wa.y); PK2(w1, wa.z, wa.w);
        PK2(w2, wb.x, wb.y); PK2(w3, wb.z, wb.w);
        PK2(w4, wc.x, wc.y); PK2(w5, wc.z, wc.w);
#pragma unroll
        for (int r = 0; r < 8; r++) {
            float h = sH[(ty * 8 + r) * HSTRIDE + k];
            unsigned long long hp;
            PK2(hp, h, h);
            FMA2(a2[r][0], hp, w0);
            FMA2(a2[r][1], hp, w1);
            FMA2(a2[r][2], hp, w2);
            FMA2(a2[r][3], hp, w3);
            FMA2(a2[r][4], hp, w4);
            FMA2(a2[r][5], hp, w5);
        }
    }

    const int ocol = tx * 12;
#pragma unroll
    for (int r = 0; r < 8; r++) {
        int atom = atom0 + ty * 8 + r;
        if (atom < NATOMS) {
            float v[12];
#pragma unroll
            for (int c = 0; c < 6; c++) UPK2(v[2 * c], v[2 * c + 1], a2[r][c]);
            float* dst = &xout[(size_t)atom * 192 + ocol];
#pragma unroll
            for (int c = 0; c < 12; c += 4) {
                float4 o;
                o.x = v[c + 0] + sB2[ocol + c + 0];
                o.y = v[c + 1] + sB2[ocol + c + 1];
                o.z = v[c + 2] + sB2[ocol + c + 2];
                o.w = v[c + 3] + sB2[ocol + c + 3];
                *(float4*)(dst + c) = o;
            }
        }
    }
}

// ---------------------------------------------------------------------------
// Kernel B: out = concat(q, mu)
// ---------------------------------------------------------------------------
__global__ __launch_bounds__(256) void painn_init_out_kernel(
    const float* __restrict__ q, const float* __restrict__ mu,
    float* __restrict__ out)
{
    const size_t NQ4 = (size_t)NATOMS * 64 / 4;
    const size_t NT4 = (size_t)NATOMS * 256 / 4;
    size_t i = (size_t)blockIdx.x * blockDim.x + threadIdx.x;
    if (i < NQ4) {
        ((float4*)out)[i] = ((const float4*)q)[i];
    } else if (i < NT4) {
        ((float4*)out)[i] = ((const float4*)mu)[i - NQ4];
    }
}

// ---------------------------------------------------------------------------
// Sort-by-j prep kernels
// ---------------------------------------------------------------------------
__global__ __launch_bounds__(256) void zero_cnt_kernel() {
    int i = blockIdx.x * blockDim.x + threadIdx.x;
    if (i < NATOMS) { g_cnt[i] = 0; g_cur[i] = 0; }
}

__global__ __launch_bounds__(256) void hist_kernel(const int* __restrict__ idx_j) {
    int e = blockIdx.x * blockDim.x + threadIdx.x;
    if (e < NEDGES) atomicAdd(&g_cnt[__ldg(&idx_j[e])], 1);
}

// one block, 1024 threads: exclusive scan of g_cnt -> g_off
__global__ __launch_bounds__(1024) void scan_kernel() {
    __shared__ int s[1024];
    const int T = 1024;
    const int t = threadIdx.x;
    const int CH = (NATOMS + T - 1) / T;   // 49
    const int base = t * CH;

    int sum = 0;
    for (int k = 0; k < CH; k++) {
        int idx = base + k;
        if (idx < NATOMS) sum += g_cnt[idx];
    }
    s[t] = sum;
    __syncthreads();
    for (int off = 1; off < T; off <<= 1) {
        int add = (t >= off) ? s[t - off] : 0;
        __syncthreads();
        s[t] += add;
        __syncthreads();
    }
    int run = s[t] - sum;   // exclusive base for this thread's chunk
    for (int k = 0; k < CH; k++) {
        int idx = base + k;
        if (idx < NATOMS) { g_off[idx] = run; run += g_cnt[idx]; }
    }
}

__global__ __launch_bounds__(256) void scatter_kernel(const int* __restrict__ idx_j) {
    int e = blockIdx.x * blockDim.x + threadIdx.x;
    if (e < NEDGES) {
        int j = __ldg(&idx_j[e]);
        int pos = g_off[j] + atomicAdd(&g_cur[j], 1);
        g_perm[pos] = e;
    }
}

// ---------------------------------------------------------------------------
// Kernel C: edge scatter, edges visited in j-sorted order (L1 reuse of x/mu).
// 16 lanes per edge, one float4 chunk per lane. red.global.add.v4.f32 scatter.
// ---------------------------------------------------------------------------
__device__ __forceinline__ void red4(float* p, float4 v) {
    asm volatile("red.global.add.v4.f32 [%0], {%1, %2, %3, %4};"
                 :: "l"(p), "f"(v.x), "f"(v.y), "f"(v.z), "f"(v.w)
                 : "memory");
}

__global__ __launch_bounds__(256) void painn_edge_kernel(
    const float* __restrict__ Wij, const float* __restrict__ dir_ij,
    const int* __restrict__ idx_i, const int* __restrict__ idx_j,
    const float* __restrict__ mu,  const float* __restrict__ x,
    float* __restrict__ out)
{
    const int gid = blockIdx.x * blockDim.x + threadIdx.x;
    const int p = gid >> 4;
    const int l = gid & 15;
    if (p >= NEDGES) return;

    const int e = __ldg(&g_perm[p]);
    const int i = __ldg(&idx_i[e]);
    const int j = __ldg(&idx_j[e]);

    const float4* W4 = (const float4*)(Wij + (size_t)e * 192);
    const float4* X4 = (const float4*)(x   + (size_t)j * 192);
    const float4* M4 = (const float4*)(mu  + (size_t)j * 192);

    const float4 w0 = __ldg(&W4[l]);
    const float4 w1 = __ldg(&W4[16 + l]);
    const float4 w2 = __ldg(&W4[32 + l]);
    const float4 x0 = __ldg(&X4[l]);
    const float4 x1 = __ldg(&X4[16 + l]);
    const float4 x2 = __ldg(&X4[32 + l]);

    const float dx = __ldg(&dir_ij[(size_t)e * 3 + 0]);
    const float dy = __ldg(&dir_ij[(size_t)e * 3 + 1]);
    const float dz = __ldg(&dir_ij[(size_t)e * 3 + 2]);

    float4 dq, mR, mM;
    dq.x = w0.x * x0.x; dq.y = w0.y * x0.y; dq.z = w0.z * x0.z; dq.w = w0.w * x0.w;
    mR.x = w1.x * x1.x; mR.y = w1.y * x1.y; mR.z = w1.z * x1.z; mR.w = w1.w * x1.w;
    mM.x = w2.x * x2.x; mM.y = w2.y * x2.y; mM.z = w2.z * x2.z; mM.w = w2.w * x2.w;

    red4(out + (size_t)i * 64 + l * 4, dq);

    const float4 m0 = __ldg(&M4[l]);
    const float4 m1 = __ldg(&M4[16 + l]);
    const float4 m2 = __ldg(&M4[32 + l]);

    float* omu = out + (size_t)NATOMS * 64 + (size_t)i * 192 + l * 4;

    float4 d0, d1, d2;
    d0.x = fmaf(mR.x, dx, mM.x * m0.x); d0.y = fmaf(mR.y, dx, mM.y * m0.y);
    d0.z = fmaf(mR.z, dx, mM.z * m0.z); d0.w = fmaf(mR.w, dx, mM.w * m0.w);
    red4(omu, d0);

    d1.x = fmaf(mR.x, dy, mM.x * m1.x); d1.y = fmaf(mR.y, dy, mM.y * m1.y);
    d1.z = fmaf(mR.z, dy, mM.z * m1.z); d1.w = fmaf(mR.w, dy, mM.w * m1.w);
    red4(omu + 64, d1);

    d2.x = fmaf(mR.x, dz, mM.x * m2.x); d2.y = fmaf(mR.y, dz, mM.y * m2.y);
    d2.z = fmaf(mR.z, dz, mM.z * m2.z); d2.w = fmaf(mR.w, dz, mM.w * m2.w);
    red4(omu + 128, d2);
}

// ---------------------------------------------------------------------------
// launch
// ---------------------------------------------------------------------------
extern "C" void kernel_launch(void* const* d_in, const int* in_sizes, int n_in,
                              void* d_out, int out_size)
{
    int iq = -1, imu = -1, iW = -1, idir = -1, ii = -1, ij = -1;
    int iW1 = -1, ib1 = -1, iW2 = -1, ib2 = -1;
    for (int k = 0; k < n_in; k++) {
        long s = in_sizes[k];
        if      (s == (long)NATOMS * 64)   iq  = k;
        else if (s == (long)NATOMS * 192)  imu = k;
        else if (s == (long)NEDGES * 192)  iW  = k;
        else if (s == (long)NEDGES * 3)    idir = k;
        else if (s == (long)NEDGES)        { if (ii < 0) ii = k; else ij = k; }
        else if (s == 64 * 64)             iW1 = k;
        else if (s == 64)                  ib1 = k;
        else if (s == 64 * 192)            iW2 = k;
        else if (s == 192)                 ib2 = k;
    }

    const float* q   = (const float*)d_in[iq];
    const float* mu  = (const float*)d_in[imu];
    const float* Wij = (const float*)d_in[iW];
    const float* dir = (const float*)d_in[idir];
    const int*  idxi = (const int*)d_in[ii];
    const int*  idxj = (const int*)d_in[ij];
    const float* W1  = (const float*)d_in[iW1];
    const float* b1  = (const float*)d_in[ib1];
    const float* W2  = (const float*)d_in[iW2];
    const float* b2  = (const float*)d_in[ib2];
    float* out = (float*)d_out;

    float* xbuf;
    cudaGetSymbolAddress((void**)&xbuf, g_x);

    // sort-by-j prep
    zero_cnt_kernel<<<(NATOMS + 255) / 256, 256>>>();
    hist_kernel<<<(NEDGES + 255) / 256, 256>>>(idxj);
    scan_kernel<<<1, 1024>>>();
    scatter_kernel<<<(NEDGES + 255) / 256, 256>>>(idxj);

    // per-atom MLP -> g_x
    painn_mlp_kernel<<<(NATOMS + 127) / 128, 256>>>(q, W1, b1, W2, b2, xbuf);

    // out = concat(q, mu)
    {
        const int total4 = NATOMS * 256 / 4;
        painn_init_out_kernel<<<(total4 + 255) / 256, 256>>>(q, mu, out);
    }

    // edge scatter in j-sorted order
    {
        const long threads = (long)NEDGES * 16;
        painn_edge_kernel<<<(int)((threads + 255) / 256), 256>>>(
            Wij, dir, idxi, idxj, mu, xbuf, out);
    }
}